// round 6
// baseline (speedup 1.0000x reference)
#include <cuda_runtime.h>
#include <math.h>

#define NU 100000
#define NI 50000
#define NT 10000
#define NNODES 160000
#define NE 800000
#define DD 64

typedef unsigned long long u64;

// ---------------- device scratch ----------------
__device__ float g_embsB[NNODES * DD];
__device__ float g_offB[NNODES * DD];
__device__ float g_EP[NNODES * 128];     // [0:64) eh=exp(h), [64:128) px=eh*x

__device__ int g_deg[NNODES];
__device__ int g_scan[NNODES];
__device__ int g_csr_off[NNODES + 1];
__device__ int g_pos[NNODES];
__device__ int g_csr_tail[NE];
__device__ int g_bsums[256];
__device__ volatile unsigned g_bar;

// ---------------- packed f32x2 helpers ----------------
__device__ __forceinline__ u64 pack2(float a, float b) {
    u64 r; asm("mov.b64 %0,{%1,%2};" : "=l"(r) : "f"(a), "f"(b)); return r;
}
__device__ __forceinline__ float2 unpack2(u64 v) {
    float2 f; asm("mov.b64 {%0,%1},%2;" : "=f"(f.x), "=f"(f.y) : "l"(v)); return f;
}
__device__ __forceinline__ u64 ffma2(u64 a, u64 b, u64 c) {
    u64 d; asm("fma.rn.f32x2 %0,%1,%2,%3;" : "=l"(d) : "l"(a), "l"(b), "l"(c)); return d;
}

// ---------------- float4 helpers ----------------
__device__ __forceinline__ void f4add(float4& a, float4 b) {
    a.x += b.x; a.y += b.y; a.z += b.z; a.w += b.w;
}
__device__ __forceinline__ void f4min_(float4& a, float4 b) {
    a.x = fminf(a.x, b.x); a.y = fminf(a.y, b.y);
    a.z = fminf(a.z, b.z); a.w = fminf(a.w, b.w);
}
__device__ __forceinline__ void f4max_(float4& a, float4 b) {
    a.x = fmaxf(a.x, b.x); a.y = fmaxf(a.y, b.y);
    a.z = fmaxf(a.z, b.z); a.w = fmaxf(a.w, b.w);
}
__device__ __forceinline__ float4 f4shfl_xor(float4 v, int m) {
    float4 r;
    r.x = __shfl_xor_sync(0xffffffffu, v.x, m);
    r.y = __shfl_xor_sync(0xffffffffu, v.y, m);
    r.z = __shfl_xor_sync(0xffffffffu, v.z, m);
    r.w = __shfl_xor_sync(0xffffffffu, v.w, m);
    return r;
}
__device__ __forceinline__ float4 f4relu(float4 v) {
    return make_float4(fmaxf(v.x, 0.f), fmaxf(v.y, 0.f), fmaxf(v.z, 0.f), fmaxf(v.w, 0.f));
}

// ---------------- persistent-grid CSR build: 120 blocks x 1024 threads ----------------
#define CSR_NB 120
#define CSR_NT 1024
#define CSR_TPT 2
#define CSR_CHUNK (CSR_NT * CSR_TPT)     // 2048 nodes per block segment

__global__ void bar_reset_kernel() {
    if (threadIdx.x == 0) g_bar = 0;
}

__device__ __forceinline__ void gbar(unsigned target) {
    __syncthreads();
    if (threadIdx.x == 0) {
        __threadfence();
        atomicAdd((unsigned*)&g_bar, 1u);
        while (g_bar < target) __nanosleep(64);
        __threadfence();
    }
    __syncthreads();
}

__global__ __launch_bounds__(CSR_NT) void csr_build_kernel(
    const int* __restrict__ head, const int* __restrict__ tail) {
    __shared__ int sh[CSR_NT];
    const int tid = threadIdx.x;
    const int b = blockIdx.x;
    const int gid = b * CSR_NT + tid;
    const int stride = CSR_NB * CSR_NT;   // 122880

    // P0: zero degrees
    for (int i = gid; i < NNODES; i += stride) g_deg[i] = 0;
    gbar(1 * CSR_NB);

    // P1: histogram by head
    for (int e = gid; e < NE; e += stride) atomicAdd(&g_deg[head[e]], 1);
    gbar(2 * CSR_NB);

    // P2: per-block segment scan + block totals
    {
        int s0 = b * CSR_CHUNK + tid * CSR_TPT;
        int v[CSR_TPT]; int tsum = 0;
#pragma unroll
        for (int i = 0; i < CSR_TPT; i++) {
            int g = s0 + i;
            v[i] = (g < NNODES) ? g_deg[g] : 0;
            tsum += v[i];
        }
        sh[tid] = tsum;
        __syncthreads();
        for (int of = 1; of < CSR_NT; of <<= 1) {
            int t = (tid >= of) ? sh[tid - of] : 0;
            __syncthreads();
            sh[tid] += t;
            __syncthreads();
        }
        int run = sh[tid] - tsum;
#pragma unroll
        for (int i = 0; i < CSR_TPT; i++) {
            run += v[i];
            int g = s0 + i;
            if (g < NNODES) g_scan[g] = run;
        }
        if (tid == CSR_NT - 1) g_bsums[b] = sh[tid];
    }
    gbar(3 * CSR_NB);

    // P3: block 0 exclusive-scans the block totals
    if (b == 0) {
        int v = (tid < CSR_NB) ? g_bsums[tid] : 0;
        sh[tid] = v;
        __syncthreads();
        for (int of = 1; of < CSR_NT; of <<= 1) {
            int t = (tid >= of) ? sh[tid - of] : 0;
            __syncthreads();
            sh[tid] += t;
            __syncthreads();
        }
        if (tid < CSR_NB) g_bsums[tid] = sh[tid] - v;
    }
    gbar(4 * CSR_NB);

    // P4: final offsets + fill cursors
    for (int g = gid; g < NNODES; g += stride) {
        int inc = g_scan[g] + g_bsums[g / CSR_CHUNK];
        g_csr_off[g + 1] = inc;
        g_pos[g] = inc - g_deg[g];
    }
    if (gid == 0) g_csr_off[0] = 0;
    gbar(5 * CSR_NB);

    // P5: scatter tails
    for (int e = gid; e < NE; e += stride) {
        int h = head[e];
        int p = atomicAdd(&g_pos[h], 1);
        g_csr_tail[p] = tail[e];
    }
}

// ---------------- fused 2-stage MLP + exp/px epilogue ----------------
__device__ __forceinline__ int wswz(int k, int j) {
    return k * 64 + ((((j >> 2) ^ (k & 15)) << 2) | (j & 3));
}

template <int LAYER>
__global__ __launch_bounds__(256) void mlp_kernel(
    const float* __restrict__ ue, const float* __restrict__ ie, const float* __restrict__ te,
    const float* __restrict__ W1, const float* __restrict__ b1,
    const float* __restrict__ W2, const float* __restrict__ b2) {
    __shared__ float Ws[64 * 64];
    __shared__ u64 Xd[64 * 64];

    int tid = threadIdx.x;
    int row0 = blockIdx.x * 64;

    for (int i = tid; i < 4096; i += 256) {
        int j = i >> 6, k = i & 63;
        Ws[wswz(k, j)] = W1[i];
    }
    for (int i = tid; i < 1024; i += 256) {
        int rl = i >> 4, c4 = (i & 15) * 4;
        int row = row0 + rl;
        const float* src;
        if (LAYER == 0) {
            if (row < NU) src = ue + (size_t)row * 64;
            else if (row < NU + NI) src = ie + (size_t)(row - NU) * 64;
            else src = te + (size_t)(row - NU - NI) * 64;
        } else {
            src = g_embsB + (size_t)row * 64;
        }
        float4 v = *(const float4*)(src + c4);
        Xd[rl * 64 + c4 + 0] = pack2(v.x, v.x);
        Xd[rl * 64 + c4 + 1] = pack2(v.y, v.y);
        Xd[rl * 64 + c4 + 2] = pack2(v.z, v.z);
        Xd[rl * 64 + c4 + 3] = pack2(v.w, v.w);
    }
    __syncthreads();

    int tx = tid & 15, ty = tid >> 4;
    int j0 = tx * 4, r0 = ty * 4;

    u64 acc[4][2];
    {
        float4 b = *(const float4*)(b1 + j0);
        u64 p0 = pack2(b.x, b.y), p1 = pack2(b.z, b.w);
#pragma unroll
        for (int i = 0; i < 4; i++) { acc[i][0] = p0; acc[i][1] = p1; }
    }

    const u64* X0 = Xd + (r0 + 0) * 64;
    const u64* X1 = Xd + (r0 + 1) * 64;
    const u64* X2 = Xd + (r0 + 2) * 64;
    const u64* X3 = Xd + (r0 + 3) * 64;

#pragma unroll 8
    for (int k = 0; k < 64; k++) {
        ulonglong2 w = *(const ulonglong2*)&Ws[k * 64 + ((tx ^ (k & 15)) << 2)];
        u64 x0 = X0[k], x1 = X1[k], x2 = X2[k], x3 = X3[k];
        acc[0][0] = ffma2(x0, w.x, acc[0][0]); acc[0][1] = ffma2(x0, w.y, acc[0][1]);
        acc[1][0] = ffma2(x1, w.x, acc[1][0]); acc[1][1] = ffma2(x1, w.y, acc[1][1]);
        acc[2][0] = ffma2(x2, w.x, acc[2][0]); acc[2][1] = ffma2(x2, w.y, acc[2][1]);
        acc[3][0] = ffma2(x3, w.x, acc[3][0]); acc[3][1] = ffma2(x3, w.y, acc[3][1]);
    }
    __syncthreads();

#pragma unroll
    for (int i = 0; i < 4; i++) {
#pragma unroll
        for (int jp = 0; jp < 2; jp++) {
            float2 p = unpack2(acc[i][jp]);
            float h0 = fmaxf(p.x, 0.f), h1 = fmaxf(p.y, 0.f);
            Xd[(r0 + i) * 64 + j0 + 2 * jp + 0] = pack2(h0, h0);
            Xd[(r0 + i) * 64 + j0 + 2 * jp + 1] = pack2(h1, h1);
        }
    }
    for (int i = tid; i < 4096; i += 256) {
        int j = i >> 6, k = i & 63;
        Ws[wswz(k, j)] = W2[i];
    }
    __syncthreads();

    {
        float4 b = *(const float4*)(b2 + j0);
        u64 p0 = pack2(b.x, b.y), p1 = pack2(b.z, b.w);
#pragma unroll
        for (int i = 0; i < 4; i++) { acc[i][0] = p0; acc[i][1] = p1; }
    }

#pragma unroll 8
    for (int k = 0; k < 64; k++) {
        ulonglong2 w = *(const ulonglong2*)&Ws[k * 64 + ((tx ^ (k & 15)) << 2)];
        u64 x0 = X0[k], x1 = X1[k], x2 = X2[k], x3 = X3[k];
        acc[0][0] = ffma2(x0, w.x, acc[0][0]); acc[0][1] = ffma2(x0, w.y, acc[0][1]);
        acc[1][0] = ffma2(x1, w.x, acc[1][0]); acc[1][1] = ffma2(x1, w.y, acc[1][1]);
        acc[2][0] = ffma2(x2, w.x, acc[2][0]); acc[2][1] = ffma2(x2, w.y, acc[2][1]);
        acc[3][0] = ffma2(x3, w.x, acc[3][0]); acc[3][1] = ffma2(x3, w.y, acc[3][1]);
    }

#pragma unroll
    for (int i = 0; i < 4; i++) {
        int row = row0 + r0 + i;
        const float* src;
        if (LAYER == 0) {
            if (row < NU) src = ue + (size_t)row * 64;
            else if (row < NU + NI) src = ie + (size_t)(row - NU) * 64;
            else src = te + (size_t)(row - NU - NI) * 64;
        } else {
            src = g_embsB + (size_t)row * 64;
        }
        float4 xv = *(const float4*)(src + j0);
        float2 u0 = unpack2(acc[i][0]);
        float2 u1 = unpack2(acc[i][1]);
        float e0 = __expf(u0.x), e1 = __expf(u0.y);
        float e2 = __expf(u1.x), e3 = __expf(u1.y);
        size_t base = (size_t)row * 128;
        *(float4*)&g_EP[base + j0]      = make_float4(e0, e1, e2, e3);
        *(float4*)&g_EP[base + 64 + j0] = make_float4(e0 * xv.x, e1 * xv.y, e2 * xv.z, e3 * xv.w);
    }
}

// ---------------- per-node aggregation: 4 edges in flight via quarter-warps ----------------
// lane = qtr*8 + li; qtr handles edge (q+qtr), li owns features [8*li, 8*li+8).
template <int FINAL>
__global__ __launch_bounds__(256) void aggregate_kernel(
    const float* __restrict__ uo, const float* __restrict__ io, const float* __restrict__ to,
    float* __restrict__ out) {
    int w = (blockIdx.x * blockDim.x + threadIdx.x) >> 5;
    if (w >= NNODES) return;
    int lane = threadIdx.x & 31;
    int qtr = lane >> 3;
    int fl = (lane & 7) * 8;

    int beg = g_csr_off[w];
    int end = g_csr_off[w + 1];
    const bool is_user = (w < NU);
    const bool is_item = (w >= NU) && (w < NU + NI);

    float4 sA = make_float4(0.f, 0.f, 0.f, 0.f), sB = sA;
    float4 nA = sA, nB = sA;
    float4 mnA = make_float4(INFINITY, INFINITY, INFINITY, INFINITY), mnB = mnA;
    float4 mxA = sA, mxB = sA;

    for (int chunk = beg; chunk < end; chunk += 32) {
        int nn = end - chunk; if (nn > 32) nn = 32;
        int tl = 0;
        if (lane < nn) tl = __ldg(&g_csr_tail[chunk + lane]);
        for (int q = 0; q < nn; q += 4) {
            int idx = q + qtr;
            int t = __shfl_sync(0xffffffffu, tl, idx & 31);
            if (idx < nn) {
                size_t epb = (size_t)t * 128 + fl;
                float4 e0 = __ldg((const float4*)&g_EP[epb]);
                float4 e1 = __ldg((const float4*)&g_EP[epb + 4]);
                float4 p0 = __ldg((const float4*)&g_EP[epb + 64]);
                float4 p1 = __ldg((const float4*)&g_EP[epb + 68]);
                f4add(sA, e0); f4add(sB, e1);
                f4add(nA, p0); f4add(nB, p1);

                bool need_off = !(is_user && t < NU);
                if (need_off) {
                    const float* op;
                    if (FINAL == 0) {
                        if (t < NU)           op = uo + (size_t)t * 64;
                        else if (t < NU + NI) op = io + (size_t)(t - NU) * 64;
                        else                  op = to + (size_t)(t - NU - NI) * 64;
                    } else {
                        op = g_offB + (size_t)t * 64;
                    }
                    float4 o0 = __ldg((const float4*)(op + fl));
                    float4 o1 = __ldg((const float4*)(op + fl + 4));
                    if (FINAL == 0) { o0 = f4relu(o0); o1 = f4relu(o1); }
                    bool t_item = (t >= NU) && (t < NU + NI);
                    bool t_tag  = (t >= NU + NI);
                    bool do_min = is_user ? t_item : (!is_item);
                    bool do_max = is_user ? t_tag  : is_item;
                    if (do_min) { f4min_(mnA, o0); f4min_(mnB, o1); }
                    if (do_max) { f4max_(mxA, o0); f4max_(mxB, o1); }
                }
            }
        }
    }

    // merge across quarter-warps (features identical across qtr)
#pragma unroll
    for (int m = 8; m <= 16; m <<= 1) {
        f4add(sA, f4shfl_xor(sA, m)); f4add(sB, f4shfl_xor(sB, m));
        f4add(nA, f4shfl_xor(nA, m)); f4add(nB, f4shfl_xor(nB, m));
        f4min_(mnA, f4shfl_xor(mnA, m)); f4min_(mnB, f4shfl_xor(mnB, m));
        f4max_(mxA, f4shfl_xor(mxA, m)); f4max_(mxB, f4shfl_xor(mxB, m));
    }

    float4 aA, aB;
    aA.x = (sA.x > 0.f) ? nA.x / sA.x : 0.f;
    aA.y = (sA.y > 0.f) ? nA.y / sA.y : 0.f;
    aA.z = (sA.z > 0.f) ? nA.z / sA.z : 0.f;
    aA.w = (sA.w > 0.f) ? nA.w / sA.w : 0.f;
    aB.x = (sB.x > 0.f) ? nB.x / sB.x : 0.f;
    aB.y = (sB.y > 0.f) ? nB.y / sB.y : 0.f;
    aB.z = (sB.z > 0.f) ? nB.z / sB.z : 0.f;
    aB.w = (sB.w > 0.f) ? nB.w / sB.w : 0.f;

    // row L2-normalize (reduce over the 8 li lanes; qtr groups identical)
    float ss = aA.x * aA.x + aA.y * aA.y + aA.z * aA.z + aA.w * aA.w
             + aB.x * aB.x + aB.y * aB.y + aB.z * aB.z + aB.w * aB.w;
#pragma unroll
    for (int of = 4; of; of >>= 1) ss += __shfl_xor_sync(0xffffffffu, ss, of);
    float inv = 1.f / fmaxf(sqrtf(ss), 1e-12f);
    aA.x *= inv; aA.y *= inv; aA.z *= inv; aA.w *= inv;
    aB.x *= inv; aB.y *= inv; aB.z *= inv; aB.w *= inv;

    float4 ovA, ovB;
    if (is_user) {
        ovA.x = fminf(isinf(mnA.x) ? 0.f : mnA.x, mxA.x);
        ovA.y = fminf(isinf(mnA.y) ? 0.f : mnA.y, mxA.y);
        ovA.z = fminf(isinf(mnA.z) ? 0.f : mnA.z, mxA.z);
        ovA.w = fminf(isinf(mnA.w) ? 0.f : mnA.w, mxA.w);
        ovB.x = fminf(isinf(mnB.x) ? 0.f : mnB.x, mxB.x);
        ovB.y = fminf(isinf(mnB.y) ? 0.f : mnB.y, mxB.y);
        ovB.z = fminf(isinf(mnB.z) ? 0.f : mnB.z, mxB.z);
        ovB.w = fminf(isinf(mnB.w) ? 0.f : mnB.w, mxB.w);
    } else if (is_item) {
        ovA = mxA; ovB = mxB;
    } else {
        ovA.x = isinf(mnA.x) ? 0.f : mnA.x;
        ovA.y = isinf(mnA.y) ? 0.f : mnA.y;
        ovA.z = isinf(mnA.z) ? 0.f : mnA.z;
        ovA.w = isinf(mnA.w) ? 0.f : mnA.w;
        ovB.x = isinf(mnB.x) ? 0.f : mnB.x;
        ovB.y = isinf(mnB.y) ? 0.f : mnB.y;
        ovB.z = isinf(mnB.z) ? 0.f : mnB.z;
        ovB.w = isinf(mnB.w) ? 0.f : mnB.w;
    }
    ovA = f4relu(ovA); ovB = f4relu(ovB);

    if (FINAL == 0) {
        size_t base = (size_t)w * 64 + fl;
        if (qtr == 0) {
            *(float4*)(g_embsB + base) = aA;
            *(float4*)(g_embsB + base + 4) = aB;
        } else if (qtr == 1) {
            *(float4*)(g_offB + base) = ovA;
            *(float4*)(g_offB + base + 4) = ovB;
        }
    } else {
        size_t eb, ob;
        if (is_user) {
            eb = (size_t)w * 64;
            ob = (size_t)NU * 64 + (size_t)w * 64;
        } else if (is_item) {
            size_t b2 = (size_t)2 * NU * 64;
            eb = b2 + (size_t)(w - NU) * 64;
            ob = b2 + (size_t)NI * 64 + (size_t)(w - NU) * 64;
        } else {
            size_t b3 = (size_t)2 * (NU + NI) * 64;
            eb = b3 + (size_t)(w - NU - NI) * 64;
            ob = b3 + (size_t)NT * 64 + (size_t)(w - NU - NI) * 64;
        }
        if (qtr == 0) {
            *(float4*)(out + eb + fl) = aA;
            *(float4*)(out + eb + fl + 4) = aB;
        } else if (qtr == 1) {
            *(float4*)(out + ob + fl) = ovA;
            *(float4*)(out + ob + fl + 4) = ovB;
        }
    }
}

// ---------------- launch ----------------
extern "C" void kernel_launch(void* const* d_in, const int* in_sizes, int n_in,
                              void* d_out, int out_size) {
    const float* user_emb = (const float*)d_in[0];
    const float* user_off = (const float*)d_in[1];
    const float* item_emb = (const float*)d_in[2];
    const float* item_off = (const float*)d_in[3];
    const float* tag_emb  = (const float*)d_in[4];
    const float* tag_off  = (const float*)d_in[5];
    const float* W1 = (const float*)d_in[6];
    const float* b1 = (const float*)d_in[7];
    const float* W2 = (const float*)d_in[8];
    const float* b2 = (const float*)d_in[9];
    const int* head = (const int*)d_in[10];
    const int* tail = (const int*)d_in[11];
    float* out = (float*)d_out;

    // slot #4 (ncu capture) = aggregate<0>
    bar_reset_kernel<<<1, 32>>>();                                          // 1
    mlp_kernel<0><<<NNODES / 64, 256>>>(user_emb, item_emb, tag_emb,
                                        W1, b1, W2, b2);                    // 2
    csr_build_kernel<<<CSR_NB, CSR_NT>>>(head, tail);                       // 3
    aggregate_kernel<0><<<(NNODES + 7) / 8, 256>>>(
        user_off, item_off, tag_off, out);                                  // 4 <- profiled
    mlp_kernel<1><<<NNODES / 64, 256>>>(user_emb, item_emb, tag_emb,
                                        W1, b1, W2, b2);                    // 5
    aggregate_kernel<1><<<(NNODES + 7) / 8, 256>>>(
        user_off, item_off, tag_off, out);                                  // 6
}

// round 8
// speedup vs baseline: 1.1027x; 1.1027x over previous
#include <cuda_runtime.h>
#include <math.h>

#define NU 100000
#define NI 50000
#define NT 10000
#define NNODES 160000
#define NE 800000
#define DD 64

typedef unsigned long long u64;

// ---------------- device scratch ----------------
__device__ float g_embsB[NNODES * DD];
__device__ float g_offB[NNODES * DD];
__device__ float g_EP[NNODES * 128];     // [0:64) eh=exp(h), [64:128) px=eh*x

__device__ int g_deg[NNODES];
__device__ int g_scan[NNODES];
__device__ int g_csr_off[NNODES + 1];
__device__ int g_pos[NNODES];
__device__ int g_csr_tail[NE];
__device__ int g_bsums[256];
__device__ volatile unsigned g_bar;

// ---------------- packed f32x2 helpers ----------------
__device__ __forceinline__ u64 pack2(float a, float b) {
    u64 r; asm("mov.b64 %0,{%1,%2};" : "=l"(r) : "f"(a), "f"(b)); return r;
}
__device__ __forceinline__ float2 unpack2(u64 v) {
    float2 f; asm("mov.b64 {%0,%1},%2;" : "=f"(f.x), "=f"(f.y) : "l"(v)); return f;
}
__device__ __forceinline__ u64 ffma2(u64 a, u64 b, u64 c) {
    u64 d; asm("fma.rn.f32x2 %0,%1,%2,%3;" : "=l"(d) : "l"(a), "l"(b), "l"(c)); return d;
}

// ---------------- persistent-grid CSR build: 120 blocks x 1024 threads ----------------
#define CSR_NB 120
#define CSR_NT 1024
#define CSR_TPT 2
#define CSR_CHUNK (CSR_NT * CSR_TPT)

__global__ void bar_reset_kernel() {
    if (threadIdx.x == 0) g_bar = 0;
}

__device__ __forceinline__ void gbar(unsigned target) {
    __syncthreads();
    if (threadIdx.x == 0) {
        __threadfence();
        atomicAdd((unsigned*)&g_bar, 1u);
        while (g_bar < target) __nanosleep(64);
        __threadfence();
    }
    __syncthreads();
}

__global__ __launch_bounds__(CSR_NT) void csr_build_kernel(
    const int* __restrict__ head, const int* __restrict__ tail) {
    __shared__ int sh[CSR_NT];
    const int tid = threadIdx.x;
    const int b = blockIdx.x;
    const int gid = b * CSR_NT + tid;
    const int stride = CSR_NB * CSR_NT;

    for (int i = gid; i < NNODES; i += stride) g_deg[i] = 0;
    gbar(1 * CSR_NB);

    for (int e = gid; e < NE; e += stride) atomicAdd(&g_deg[head[e]], 1);
    gbar(2 * CSR_NB);

    {
        int s0 = b * CSR_CHUNK + tid * CSR_TPT;
        int v[CSR_TPT]; int tsum = 0;
#pragma unroll
        for (int i = 0; i < CSR_TPT; i++) {
            int g = s0 + i;
            v[i] = (g < NNODES) ? g_deg[g] : 0;
            tsum += v[i];
        }
        sh[tid] = tsum;
        __syncthreads();
        for (int of = 1; of < CSR_NT; of <<= 1) {
            int t = (tid >= of) ? sh[tid - of] : 0;
            __syncthreads();
            sh[tid] += t;
            __syncthreads();
        }
        int run = sh[tid] - tsum;
#pragma unroll
        for (int i = 0; i < CSR_TPT; i++) {
            run += v[i];
            int g = s0 + i;
            if (g < NNODES) g_scan[g] = run;
        }
        if (tid == CSR_NT - 1) g_bsums[b] = sh[tid];
    }
    gbar(3 * CSR_NB);

    if (b == 0) {
        int v = (tid < CSR_NB) ? g_bsums[tid] : 0;
        sh[tid] = v;
        __syncthreads();
        for (int of = 1; of < CSR_NT; of <<= 1) {
            int t = (tid >= of) ? sh[tid - of] : 0;
            __syncthreads();
            sh[tid] += t;
            __syncthreads();
        }
        if (tid < CSR_NB) g_bsums[tid] = sh[tid] - v;
    }
    gbar(4 * CSR_NB);

    for (int g = gid; g < NNODES; g += stride) {
        int inc = g_scan[g] + g_bsums[g / CSR_CHUNK];
        g_csr_off[g + 1] = inc;
        g_pos[g] = inc - g_deg[g];
    }
    if (gid == 0) g_csr_off[0] = 0;
    gbar(5 * CSR_NB);

    for (int e = gid; e < NE; e += stride) {
        int h = head[e];
        int p = atomicAdd(&g_pos[h], 1);
        g_csr_tail[p] = tail[e];
    }
}

// ---------------- fused 2-stage MLP + exp/px epilogue (split EP layout) ----------------
__device__ __forceinline__ int wswz(int k, int j) {
    return k * 64 + ((((j >> 2) ^ (k & 15)) << 2) | (j & 3));
}

template <int LAYER>
__global__ __launch_bounds__(256) void mlp_kernel(
    const float* __restrict__ ue, const float* __restrict__ ie, const float* __restrict__ te,
    const float* __restrict__ W1, const float* __restrict__ b1,
    const float* __restrict__ W2, const float* __restrict__ b2) {
    __shared__ float Ws[64 * 64];
    __shared__ u64 Xd[64 * 64];

    int tid = threadIdx.x;
    int row0 = blockIdx.x * 64;

    for (int i = tid; i < 4096; i += 256) {
        int j = i >> 6, k = i & 63;
        Ws[wswz(k, j)] = W1[i];
    }
    for (int i = tid; i < 1024; i += 256) {
        int rl = i >> 4, c4 = (i & 15) * 4;
        int row = row0 + rl;
        const float* src;
        if (LAYER == 0) {
            if (row < NU) src = ue + (size_t)row * 64;
            else if (row < NU + NI) src = ie + (size_t)(row - NU) * 64;
            else src = te + (size_t)(row - NU - NI) * 64;
        } else {
            src = g_embsB + (size_t)row * 64;
        }
        float4 v = *(const float4*)(src + c4);
        Xd[rl * 64 + c4 + 0] = pack2(v.x, v.x);
        Xd[rl * 64 + c4 + 1] = pack2(v.y, v.y);
        Xd[rl * 64 + c4 + 2] = pack2(v.z, v.z);
        Xd[rl * 64 + c4 + 3] = pack2(v.w, v.w);
    }
    __syncthreads();

    int tx = tid & 15, ty = tid >> 4;
    int j0 = tx * 4, r0 = ty * 4;

    u64 acc[4][2];
    {
        float4 b = *(const float4*)(b1 + j0);
        u64 p0 = pack2(b.x, b.y), p1 = pack2(b.z, b.w);
#pragma unroll
        for (int i = 0; i < 4; i++) { acc[i][0] = p0; acc[i][1] = p1; }
    }

    const u64* X0 = Xd + (r0 + 0) * 64;
    const u64* X1 = Xd + (r0 + 1) * 64;
    const u64* X2 = Xd + (r0 + 2) * 64;
    const u64* X3 = Xd + (r0 + 3) * 64;

#pragma unroll 8
    for (int k = 0; k < 64; k++) {
        ulonglong2 w = *(const ulonglong2*)&Ws[k * 64 + ((tx ^ (k & 15)) << 2)];
        u64 x0 = X0[k], x1 = X1[k], x2 = X2[k], x3 = X3[k];
        acc[0][0] = ffma2(x0, w.x, acc[0][0]); acc[0][1] = ffma2(x0, w.y, acc[0][1]);
        acc[1][0] = ffma2(x1, w.x, acc[1][0]); acc[1][1] = ffma2(x1, w.y, acc[1][1]);
        acc[2][0] = ffma2(x2, w.x, acc[2][0]); acc[2][1] = ffma2(x2, w.y, acc[2][1]);
        acc[3][0] = ffma2(x3, w.x, acc[3][0]); acc[3][1] = ffma2(x3, w.y, acc[3][1]);
    }
    __syncthreads();

#pragma unroll
    for (int i = 0; i < 4; i++) {
#pragma unroll
        for (int jp = 0; jp < 2; jp++) {
            float2 p = unpack2(acc[i][jp]);
            float h0 = fmaxf(p.x, 0.f), h1 = fmaxf(p.y, 0.f);
            Xd[(r0 + i) * 64 + j0 + 2 * jp + 0] = pack2(h0, h0);
            Xd[(r0 + i) * 64 + j0 + 2 * jp + 1] = pack2(h1, h1);
        }
    }
    for (int i = tid; i < 4096; i += 256) {
        int j = i >> 6, k = i & 63;
        Ws[wswz(k, j)] = W2[i];
    }
    __syncthreads();

    {
        float4 b = *(const float4*)(b2 + j0);
        u64 p0 = pack2(b.x, b.y), p1 = pack2(b.z, b.w);
#pragma unroll
        for (int i = 0; i < 4; i++) { acc[i][0] = p0; acc[i][1] = p1; }
    }

#pragma unroll 8
    for (int k = 0; k < 64; k++) {
        ulonglong2 w = *(const ulonglong2*)&Ws[k * 64 + ((tx ^ (k & 15)) << 2)];
        u64 x0 = X0[k], x1 = X1[k], x2 = X2[k], x3 = X3[k];
        acc[0][0] = ffma2(x0, w.x, acc[0][0]); acc[0][1] = ffma2(x0, w.y, acc[0][1]);
        acc[1][0] = ffma2(x1, w.x, acc[1][0]); acc[1][1] = ffma2(x1, w.y, acc[1][1]);
        acc[2][0] = ffma2(x2, w.x, acc[2][0]); acc[2][1] = ffma2(x2, w.y, acc[2][1]);
        acc[3][0] = ffma2(x3, w.x, acc[3][0]); acc[3][1] = ffma2(x3, w.y, acc[3][1]);
    }

    // epilogue: eh = exp(y) at [0:64), px = eh * x at [64:128)
#pragma unroll
    for (int i = 0; i < 4; i++) {
        int row = row0 + r0 + i;
        const float* src;
        if (LAYER == 0) {
            if (row < NU) src = ue + (size_t)row * 64;
            else if (row < NU + NI) src = ie + (size_t)(row - NU) * 64;
            else src = te + (size_t)(row - NU - NI) * 64;
        } else {
            src = g_embsB + (size_t)row * 64;
        }
        float4 xv = *(const float4*)(src + j0);
        float2 u0 = unpack2(acc[i][0]);
        float2 u1 = unpack2(acc[i][1]);
        float e0 = __expf(u0.x), e1 = __expf(u0.y);
        float e2 = __expf(u1.x), e3 = __expf(u1.y);
        size_t base = (size_t)row * 128;
        *(float4*)&g_EP[base + j0]      = make_float4(e0, e1, e2, e3);
        *(float4*)&g_EP[base + 64 + j0] = make_float4(e0 * xv.x, e1 * xv.y, e2 * xv.z, e3 * xv.w);
    }
}

// ---------------- per-node aggregation (proven R5 shape + unroll 4) ----------------
// One warp per node; lanes 0-15 even edge, 16-31 odd edge; lane owns 4 features.
template <int FINAL>
__global__ __launch_bounds__(256) void aggregate_kernel(
    const float* __restrict__ uo, const float* __restrict__ io, const float* __restrict__ to,
    float* __restrict__ out) {
    int w = (blockIdx.x * blockDim.x + threadIdx.x) >> 5;
    if (w >= NNODES) return;
    int lane = threadIdx.x & 31;
    int half = lane >> 4;
    int fl = (lane & 15) * 4;

    int beg = g_csr_off[w];
    int end = g_csr_off[w + 1];
    const bool is_user = (w < NU);
    const bool is_item = (w >= NU) && (w < NU + NI);

    float4 s = make_float4(0.f, 0.f, 0.f, 0.f);
    float4 n = make_float4(0.f, 0.f, 0.f, 0.f);
    float4 mn = make_float4(INFINITY, INFINITY, INFINITY, INFINITY);
    float4 mx = make_float4(0.f, 0.f, 0.f, 0.f);

    for (int chunk = beg; chunk < end; chunk += 32) {
        int nn = end - chunk; if (nn > 32) nn = 32;
        int tl = 0;
        if (lane < nn) tl = __ldg(&g_csr_tail[chunk + lane]);
#pragma unroll 4
        for (int q = 0; q < nn; q += 2) {
            int idx = q + half;
            int t = __shfl_sync(0xffffffffu, tl, idx & 31);
            if (idx < nn) {
                size_t epb = (size_t)t * 128;
                float4 eh = __ldg((const float4*)&g_EP[epb + fl]);
                float4 px = __ldg((const float4*)&g_EP[epb + 64 + fl]);

                s.x += eh.x; s.y += eh.y; s.z += eh.z; s.w += eh.w;
                n.x += px.x; n.y += px.y; n.z += px.z; n.w += px.w;

                bool need_off = !(is_user && t < NU);
                if (need_off) {
                    const float* op;
                    if (FINAL == 0) {
                        if (t < NU)           op = uo + (size_t)t * 64;
                        else if (t < NU + NI) op = io + (size_t)(t - NU) * 64;
                        else                  op = to + (size_t)(t - NU - NI) * 64;
                    } else {
                        op = g_offB + (size_t)t * 64;
                    }
                    float4 o = __ldg((const float4*)(op + fl));
                    if (FINAL == 0) {
                        o.x = fmaxf(o.x, 0.f); o.y = fmaxf(o.y, 0.f);
                        o.z = fmaxf(o.z, 0.f); o.w = fmaxf(o.w, 0.f);
                    }
                    bool t_item = (t >= NU) && (t < NU + NI);
                    bool t_tag  = (t >= NU + NI);
                    bool do_min = is_user ? t_item : (!is_item);
                    bool do_max = is_user ? t_tag  : is_item;
                    if (do_min) {
                        mn.x = fminf(mn.x, o.x); mn.y = fminf(mn.y, o.y);
                        mn.z = fminf(mn.z, o.z); mn.w = fminf(mn.w, o.w);
                    }
                    if (do_max) {
                        mx.x = fmaxf(mx.x, o.x); mx.y = fmaxf(mx.y, o.y);
                        mx.z = fmaxf(mx.z, o.z); mx.w = fmaxf(mx.w, o.w);
                    }
                }
            }
        }
    }

#define MRG_ADD(v) v += __shfl_xor_sync(0xffffffffu, v, 16)
#define MRG_MIN(v) v = fminf(v, __shfl_xor_sync(0xffffffffu, v, 16))
#define MRG_MAX(v) v = fmaxf(v, __shfl_xor_sync(0xffffffffu, v, 16))
    MRG_ADD(s.x); MRG_ADD(s.y); MRG_ADD(s.z); MRG_ADD(s.w);
    MRG_ADD(n.x); MRG_ADD(n.y); MRG_ADD(n.z); MRG_ADD(n.w);
    MRG_MIN(mn.x); MRG_MIN(mn.y); MRG_MIN(mn.z); MRG_MIN(mn.w);
    MRG_MAX(mx.x); MRG_MAX(mx.y); MRG_MAX(mx.z); MRG_MAX(mx.w);

    float4 a;
    a.x = (s.x > 0.f) ? n.x / s.x : 0.f;
    a.y = (s.y > 0.f) ? n.y / s.y : 0.f;
    a.z = (s.z > 0.f) ? n.z / s.z : 0.f;
    a.w = (s.w > 0.f) ? n.w / s.w : 0.f;

    float ss = a.x * a.x + a.y * a.y + a.z * a.z + a.w * a.w;
#pragma unroll
    for (int of = 8; of; of >>= 1) ss += __shfl_xor_sync(0xffffffffu, ss, of);
    float inv = 1.f / fmaxf(sqrtf(ss), 1e-12f);
    a.x *= inv; a.y *= inv; a.z *= inv; a.w *= inv;

    float4 ov;
    if (is_user) {
        float i0 = isinf(mn.x) ? 0.f : mn.x;
        float i1 = isinf(mn.y) ? 0.f : mn.y;
        float i2 = isinf(mn.z) ? 0.f : mn.z;
        float i3 = isinf(mn.w) ? 0.f : mn.w;
        ov = make_float4(fminf(i0, mx.x), fminf(i1, mx.y), fminf(i2, mx.z), fminf(i3, mx.w));
    } else if (is_item) {
        ov = mx;
    } else {
        ov.x = isinf(mn.x) ? 0.f : mn.x;
        ov.y = isinf(mn.y) ? 0.f : mn.y;
        ov.z = isinf(mn.z) ? 0.f : mn.z;
        ov.w = isinf(mn.w) ? 0.f : mn.w;
    }
    ov.x = fmaxf(ov.x, 0.f); ov.y = fmaxf(ov.y, 0.f);
    ov.z = fmaxf(ov.z, 0.f); ov.w = fmaxf(ov.w, 0.f);

    if (FINAL == 0) {
        size_t base = (size_t)w * 64 + fl;
        if (half == 0) *(float4*)(g_embsB + base) = a;
        else           *(float4*)(g_offB + base)  = ov;
    } else {
        size_t eb, ob;
        if (is_user) {
            eb = (size_t)w * 64;
            ob = (size_t)NU * 64 + (size_t)w * 64;
        } else if (is_item) {
            size_t b2 = (size_t)2 * NU * 64;
            eb = b2 + (size_t)(w - NU) * 64;
            ob = b2 + (size_t)NI * 64 + (size_t)(w - NU) * 64;
        } else {
            size_t b3 = (size_t)2 * (NU + NI) * 64;
            eb = b3 + (size_t)(w - NU - NI) * 64;
            ob = b3 + (size_t)NT * 64 + (size_t)(w - NU - NI) * 64;
        }
        if (half == 0) *(float4*)(out + eb + fl) = a;
        else           *(float4*)(out + ob + fl) = ov;
    }
}

// ---------------- launch ----------------
extern "C" void kernel_launch(void* const* d_in, const int* in_sizes, int n_in,
                              void* d_out, int out_size) {
    const float* user_emb = (const float*)d_in[0];
    const float* user_off = (const float*)d_in[1];
    const float* item_emb = (const float*)d_in[2];
    const float* item_off = (const float*)d_in[3];
    const float* tag_emb  = (const float*)d_in[4];
    const float* tag_off  = (const float*)d_in[5];
    const float* W1 = (const float*)d_in[6];
    const float* b1 = (const float*)d_in[7];
    const float* W2 = (const float*)d_in[8];
    const float* b2 = (const float*)d_in[9];
    const int* head = (const int*)d_in[10];
    const int* tail = (const int*)d_in[11];
    float* out = (float*)d_out;

    // slot #4 (ncu capture) = aggregate<0>
    bar_reset_kernel<<<1, 32>>>();                                          // 1
    mlp_kernel<0><<<NNODES / 64, 256>>>(user_emb, item_emb, tag_emb,
                                        W1, b1, W2, b2);                    // 2
    csr_build_kernel<<<CSR_NB, CSR_NT>>>(head, tail);                       // 3
    aggregate_kernel<0><<<(NNODES + 7) / 8, 256>>>(
        user_off, item_off, tag_off, out);                                  // 4 <- profiled
    mlp_kernel<1><<<NNODES / 64, 256>>>(user_emb, item_emb, tag_emb,
                                        W1, b1, W2, b2);                    // 5
    aggregate_kernel<1><<<(NNODES + 7) / 8, 256>>>(
        user_off, item_off, tag_off, out);                                  // 6
}